// round 14
// baseline (speedup 1.0000x reference)
#include <cuda_runtime.h>
#include <cuda_bf16.h>
#include <cstdint>
#include <cstddef>

#define BATCH 64
#define CH    512
#define LSEQ  512
#define MAT   (CH * LSEQ)
#define NMAT  (BATCH * MAT)
#define EPS   1e-5f

// ---------------- scratch -----------------------------------------------------
__device__ float    g_Y[3ULL * NMAT];        // Q,K,VT pre-BN fp32
__device__ float    g_Wsc[NMAT];             // scores fp32
__device__ uint16_t g_bf[12ULL * NMAT];      // QH,QL,KH,KL,VH,VL,WH,WL,X0H,X0L,X1H,X1L
__device__ uint16_t g_wth[9ULL * MAT];
__device__ uint16_t g_wtl[9ULL * MAT];
__device__ float g_sum[3 * CH];
__device__ float g_sq[3 * CH];

// ---------------- helpers ------------------------------------------------------
__device__ __forceinline__ uint32_t packbf(float a, float b) {
    __nv_bfloat162 t = __floats2bfloat162_rn(a, b);
    return *reinterpret_cast<uint32_t*>(&t);
}
__device__ __forceinline__ float bf16rt(float x) {
    return __bfloat162float(__float2bfloat16(x));
}

#define LDSM4(R, addr) \
    asm volatile("ldmatrix.sync.aligned.m8n8.x4.shared.b16 {%0,%1,%2,%3}, [%4];" \
        : "=r"((R)[0]), "=r"((R)[1]), "=r"((R)[2]), "=r"((R)[3]) : "r"(addr))

__device__ __forceinline__ void mma16816(float* d, const uint32_t* a,
                                         uint32_t b0, uint32_t b1) {
    asm volatile(
        "mma.sync.aligned.m16n8k16.row.col.f32.bf16.bf16.f32 "
        "{%0,%1,%2,%3}, {%4,%5,%6,%7}, {%8,%9}, {%0,%1,%2,%3};"
        : "+f"(d[0]), "+f"(d[1]), "+f"(d[2]), "+f"(d[3])
        : "r"(a[0]), "r"(a[1]), "r"(a[2]), "r"(a[3]), "r"(b0), "r"(b1));
}

#define CP16(dst, src) \
    asm volatile("cp.async.cg.shared.global [%0], [%1], 16;" :: "r"(dst), "l"(src))
#define CPCOMMIT() asm volatile("cp.async.commit_group;" ::: "memory")
#define CPWAIT1()  asm volatile("cp.async.wait_group 1;" ::: "memory")

// ---------------- GEMM core (NT, bf16x3, pre-split operands) -------------------
#define KC 32
#define TILE_B  8192
#define STAGE_B 32768
#define SMEM_DYN (3 * STAGE_B)

__device__ __forceinline__ void gemm_core(
    const uint16_t* __restrict__ Ah, const uint16_t* __restrict__ Al,
    const uint16_t* __restrict__ Bh, const uint16_t* __restrict__ Bl,
    float* __restrict__ CfB, uint16_t* __restrict__ ChB, uint16_t* __restrict__ ClB,
    const float* __restrict__ bias,
    float* __restrict__ sums, float* __restrict__ sqs,
    int m0, int n0, int outMode)
{
    extern __shared__ uint8_t smraw[];
    const uint32_t smemu = (uint32_t)__cvta_generic_to_shared(smraw);
    const int tid  = threadIdx.x;
    const int lane = tid & 31, wid = tid >> 5;

    const int r0 = tid >> 2, k0 = tid & 3;
    const uint32_t dst0 = (uint32_t)(r0 * 64 + ((k0 ^ ((r0 >> 1) & 3)) << 4));
    const char* aH0 = (const char*)(Ah + (size_t)(m0 + r0) * 512 + k0 * 8);
    const char* aL0 = (const char*)(Al + (size_t)(m0 + r0) * 512 + k0 * 8);
    const char* bH0 = (const char*)(Bh + (size_t)(n0 + r0) * 512 + k0 * 8);
    const char* bL0 = (const char*)(Bl + (size_t)(n0 + r0) * 512 + k0 * 8);

    auto issue = [&](int s, int c) {
        const uint32_t sb = smemu + (uint32_t)s * STAGE_B;
        const size_t o = (size_t)c * (KC * 2);
#pragma unroll
        for (int p = 0; p < 4; p++) {
            const uint32_t d = sb + dst0 + p * 2048;
            const size_t so = o + (size_t)p * 32768;
            CP16(d,              aH0 + so);
            CP16(d + TILE_B,     aL0 + so);
            CP16(d + 2 * TILE_B, bH0 + so);
            CP16(d + 3 * TILE_B, bL0 + so);
        }
    };

    const int mw = (wid & 1) * 64;
    const int nw = (wid >> 1) * 64;
    const int lrow = (lane & 7) + 8 * ((lane >> 3) & 1);
    const int lk16 = lane >> 4;
    uint32_t offA[4][2], offB[4][2];
#pragma unroll
    for (int fi = 0; fi < 4; fi++) {
        const int row = mw + fi * 16 + lrow;
        const uint32_t sw = (row >> 1) & 3;
        offA[fi][0] = (uint32_t)(row * 64 + (((0 + lk16) ^ sw) << 4));
        offA[fi][1] = (uint32_t)(row * 64 + (((2 + lk16) ^ sw) << 4));
    }
#pragma unroll
    for (int bj = 0; bj < 4; bj++) {
        const int row = nw + bj * 16 + lrow;
        const uint32_t sw = (row >> 1) & 3;
        offB[bj][0] = (uint32_t)(row * 64 + (((0 + lk16) ^ sw) << 4));
        offB[bj][1] = (uint32_t)(row * 64 + (((2 + lk16) ^ sw) << 4));
    }

    float acc[4][8][4];
#pragma unroll
    for (int i = 0; i < 4; i++)
#pragma unroll
        for (int j = 0; j < 8; j++)
#pragma unroll
            for (int e = 0; e < 4; e++) acc[i][j][e] = 0.f;

    auto compute = [&](int s) {
        const uint32_t sb = smemu + (uint32_t)s * STAGE_B;
#pragma unroll
        for (int kg = 0; kg < 2; kg++) {
            uint32_t Ahr[4][4], Bhr[4][4], Blr[4][4], Alr[4][4];
#pragma unroll
            for (int fi = 0; fi < 4; fi++)
                LDSM4(Ahr[fi], sb + offA[fi][kg]);
#pragma unroll
            for (int bj = 0; bj < 4; bj++)
                LDSM4(Bhr[bj], sb + 2 * TILE_B + offB[bj][kg]);
#pragma unroll
            for (int i = 0; i < 4; i++)
#pragma unroll
                for (int j = 0; j < 8; j++)
                    mma16816(acc[i][j], Ahr[i], Bhr[j >> 1][j & 1], Bhr[j >> 1][(j & 1) + 2]);
#pragma unroll
            for (int bj = 0; bj < 4; bj++)
                LDSM4(Blr[bj], sb + 3 * TILE_B + offB[bj][kg]);
#pragma unroll
            for (int i = 0; i < 4; i++)
#pragma unroll
                for (int j = 0; j < 8; j++)
                    mma16816(acc[i][j], Ahr[i], Blr[j >> 1][j & 1], Blr[j >> 1][(j & 1) + 2]);
#pragma unroll
            for (int fi = 0; fi < 4; fi++)
                LDSM4(Alr[fi], sb + TILE_B + offA[fi][kg]);
#pragma unroll
            for (int i = 0; i < 4; i++)
#pragma unroll
                for (int j = 0; j < 8; j++)
                    mma16816(acc[i][j], Alr[i], Bhr[j >> 1][j & 1], Bhr[j >> 1][(j & 1) + 2]);
        }
    };

    issue(0, 0); CPCOMMIT();
    issue(1, 1); CPCOMMIT();

#pragma unroll 1
    for (int c = 0; c < 16; c++) {
        CPWAIT1();
        __syncthreads();
        if (c + 2 < 16) issue((c + 2) % 3, c + 2);
        CPCOMMIT();
        compute(c % 3);
    }

    // ---------------- epilogue ----------------
    const int rg = lane >> 2;
    const int cg = (lane & 3) * 2;

    float bc[16], cs[16], cq[16];
    if (outMode == 2) {
#pragma unroll
        for (int j = 0; j < 8; j++) {
            bc[2 * j]     = bias[n0 + nw + j * 8 + cg];
            bc[2 * j + 1] = bias[n0 + nw + j * 8 + cg + 1];
        }
#pragma unroll
        for (int e = 0; e < 16; e++) { cs[e] = 0.f; cq[e] = 0.f; }
    }

#pragma unroll
    for (int i = 0; i < 4; i++) {
        const int row0 = m0 + mw + i * 16 + rg;
        const int row1 = row0 + 8;
        float bv0 = 0.f, bv1 = 0.f;
        if (outMode == 1) { bv0 = bias[row0]; bv1 = bias[row1]; }
        float s0 = 0.f, q0 = 0.f, s1 = 0.f, q1 = 0.f;
#pragma unroll
        for (int j = 0; j < 8; j++) {
            float* cc = acc[i][j];
            if (outMode == 1) { cc[0] += bv0; cc[1] += bv0; cc[2] += bv1; cc[3] += bv1; }
            if (outMode == 2) {
                cc[0] += bc[2 * j]; cc[1] += bc[2 * j + 1];
                cc[2] += bc[2 * j]; cc[3] += bc[2 * j + 1];
            }
            const int col = n0 + nw + j * 8 + cg;
            if (outMode == 3) {
                uint32_t* H = (uint32_t*)ChB;
                uint32_t* L = (uint32_t*)ClB;
                const size_t i0 = ((size_t)row0 * 512 + col) >> 1;
                const size_t i1 = ((size_t)row1 * 512 + col) >> 1;
                H[i0] = packbf(cc[0], cc[1]);
                L[i0] = packbf(cc[0] - bf16rt(cc[0]), cc[1] - bf16rt(cc[1]));
                H[i1] = packbf(cc[2], cc[3]);
                L[i1] = packbf(cc[2] - bf16rt(cc[2]), cc[3] - bf16rt(cc[3]));
            } else {
                *(float2*)&CfB[(size_t)row0 * 512 + col] = make_float2(cc[0], cc[1]);
                *(float2*)&CfB[(size_t)row1 * 512 + col] = make_float2(cc[2], cc[3]);
            }
            if (outMode == 1) {
                s0 += cc[0] + cc[1]; q0 += cc[0] * cc[0] + cc[1] * cc[1];
                s1 += cc[2] + cc[3]; q1 += cc[2] * cc[2] + cc[3] * cc[3];
            }
            if (outMode == 2) {
                cs[2 * j]     += cc[0] + cc[2];
                cs[2 * j + 1] += cc[1] + cc[3];
                cq[2 * j]     += cc[0] * cc[0] + cc[2] * cc[2];
                cq[2 * j + 1] += cc[1] * cc[1] + cc[3] * cc[3];
            }
        }
        if (outMode == 1) {
#pragma unroll
            for (int off = 1; off <= 2; off <<= 1) {
                s0 += __shfl_xor_sync(0xffffffffu, s0, off);
                q0 += __shfl_xor_sync(0xffffffffu, q0, off);
                s1 += __shfl_xor_sync(0xffffffffu, s1, off);
                q1 += __shfl_xor_sync(0xffffffffu, q1, off);
            }
            if ((lane & 3) == 0) {
                atomicAdd(&sums[row0], s0); atomicAdd(&sqs[row0], q0);
                atomicAdd(&sums[row1], s1); atomicAdd(&sqs[row1], q1);
            }
        }
    }
    if (outMode == 2) {
#pragma unroll
        for (int e = 0; e < 16; e++) {
#pragma unroll
            for (int off = 4; off <= 16; off <<= 1) {
                cs[e] += __shfl_xor_sync(0xffffffffu, cs[e], off);
                cq[e] += __shfl_xor_sync(0xffffffffu, cq[e], off);
            }
        }
        if (rg == 0) {
#pragma unroll
            for (int j = 0; j < 8; j++) {
                const int col = n0 + nw + j * 8 + cg;
                atomicAdd(&sums[col], cs[2 * j]);         atomicAdd(&sqs[col], cq[2 * j]);
                atomicAdd(&sums[col + 1], cs[2 * j + 1]); atomicAdd(&sqs[col + 1], cq[2 * j + 1]);
            }
        }
    }
}

// standalone GEMM (scores / AV), full per-batch grids
__global__ __launch_bounds__(128, 2) void gemm_bf3(
    const uint16_t* __restrict__ Ah, const uint16_t* __restrict__ Al, int strideA,
    const uint16_t* __restrict__ Bh, const uint16_t* __restrict__ Bl, int strideB,
    float* __restrict__ Cf,
    uint16_t* __restrict__ Ch, uint16_t* __restrict__ Cl,
    int outMode)
{
    const int b = blockIdx.z;
    gemm_core(Ah + (size_t)b * strideA, Al + (size_t)b * strideA,
              Bh + (size_t)b * strideB, Bl + (size_t)b * strideB,
              Cf ? Cf + (size_t)b * MAT : nullptr,
              Ch ? Ch + (size_t)b * MAT : nullptr,
              Cl ? Cl + (size_t)b * MAT : nullptr,
              nullptr, nullptr, nullptr,
              blockIdx.y * 128, blockIdx.x * 128, outMode);
}

// fused Q+K projection GEMM: z in [0,128), proj = z>>6, batch = z&63  (mode 1)
__global__ __launch_bounds__(128, 2) void projQK_gemm(
    const uint16_t* __restrict__ wqh, const uint16_t* __restrict__ wql,
    const uint16_t* __restrict__ wkh, const uint16_t* __restrict__ wkl,
    const uint16_t* __restrict__ XiH, const uint16_t* __restrict__ XiL,
    float* __restrict__ Yq, float* __restrict__ Yk,
    const float* __restrict__ bq, const float* __restrict__ bk,
    float* __restrict__ sum, float* __restrict__ sq)
{
    const int proj = blockIdx.z >> 6;
    const int b    = blockIdx.z & 63;
    const size_t xo = (size_t)b * MAT;
    if (proj == 0)
        gemm_core(wqh, wql, XiH + xo, XiL + xo, Yq + xo, nullptr, nullptr,
                  bq, sum, sq, blockIdx.y * 128, blockIdx.x * 128, 1);
    else
        gemm_core(wkh, wkl, XiH + xo, XiL + xo, Yk + xo, nullptr, nullptr,
                  bk, sum + CH, sq + CH, blockIdx.y * 128, blockIdx.x * 128, 1);
}

// V projection GEMM (mode 2, col-stats)
__global__ __launch_bounds__(128, 2) void projV_gemm(
    const uint16_t* __restrict__ XiH, const uint16_t* __restrict__ XiL,
    const uint16_t* __restrict__ wvh, const uint16_t* __restrict__ wvl,
    float* __restrict__ Yv, const float* __restrict__ bv,
    float* __restrict__ sums, float* __restrict__ sqs)
{
    const size_t xo = (size_t)blockIdx.z * MAT;
    gemm_core(XiH + xo, XiL + xo, wvh, wvl, Yv + xo, nullptr, nullptr,
              bv, sums, sqs, blockIdx.y * 128, blockIdx.x * 128, 2);
}

// ---------------- elementwise kernels -------------------------------------------
__global__ void transpose_split(const float* __restrict__ src,
                                uint16_t* __restrict__ H, uint16_t* __restrict__ L)
{
    __shared__ float t[32][33];
    const int b = blockIdx.z;
    const int x0 = blockIdx.x * 32;
    const int y0 = blockIdx.y * 32;
    const float* S = src + (size_t)b * MAT;
    const int tx = threadIdx.x, ty = threadIdx.y;
#pragma unroll
    for (int j = 0; j < 32; j += 8)
        t[ty + j][tx] = S[(size_t)(y0 + ty + j) * 512 + x0 + tx];
    __syncthreads();
    uint16_t* Hb = H + (size_t)b * MAT;
    uint16_t* Lb = L + (size_t)b * MAT;
#pragma unroll
    for (int j = 0; j < 32; j += 8) {
        float v = t[tx][ty + j];
        float h = bf16rt(v);
        const size_t idx = (size_t)(x0 + ty + j) * 512 + y0 + tx;
        __nv_bfloat16 hb = __float2bfloat16(v);
        __nv_bfloat16 lb = __float2bfloat16(v - h);
        Hb[idx] = *reinterpret_cast<uint16_t*>(&hb);
        Lb[idx] = *reinterpret_cast<uint16_t*>(&lb);
    }
}

__global__ void cvt_split3(const float* __restrict__ Wq, const float* __restrict__ Wk,
                           const float* __restrict__ Wv,
                           uint16_t* __restrict__ Hall, uint16_t* __restrict__ Lall)
{
    const int w = blockIdx.y;
    const float* src = (w == 0) ? Wq : (w == 1) ? Wk : Wv;
    uint16_t* H = Hall + (size_t)w * 3 * MAT;
    uint16_t* L = Lall + (size_t)w * 3 * MAT;
    const size_t i = (size_t)blockIdx.x * blockDim.x + threadIdx.x;
    float4 v0 = ((const float4*)src)[2 * i];
    float4 v1 = ((const float4*)src)[2 * i + 1];
    uint4 h, l;
    h.x = packbf(v0.x, v0.y); h.y = packbf(v0.z, v0.w);
    h.z = packbf(v1.x, v1.y); h.w = packbf(v1.z, v1.w);
    l.x = packbf(v0.x - bf16rt(v0.x), v0.y - bf16rt(v0.y));
    l.y = packbf(v0.z - bf16rt(v0.z), v0.w - bf16rt(v0.w));
    l.z = packbf(v1.x - bf16rt(v1.x), v1.y - bf16rt(v1.y));
    l.w = packbf(v1.z - bf16rt(v1.z), v1.w - bf16rt(v1.w));
    ((uint4*)H)[i] = h;
    ((uint4*)L)[i] = l;
}

__global__ void zero_stats()
{
    int i = blockIdx.x * blockDim.x + threadIdx.x;
    if (i < 3 * CH) { g_sum[i] = 0.f; g_sq[i] = 0.f; }
}

// BN+ReLU+split for Q,K (row layout), 8 elems/thread, inline finalize; y selects Q/K
__global__ void bnqk_split8(
    const float* __restrict__ Yq, const float* __restrict__ Yk,
    const float* __restrict__ gq, const float* __restrict__ betaq,
    const float* __restrict__ gk, const float* __restrict__ betak,
    uint16_t* __restrict__ QH, uint16_t* __restrict__ QL,
    uint16_t* __restrict__ KH, uint16_t* __restrict__ KL)
{
    const size_t i = (size_t)blockIdx.x * blockDim.x + threadIdx.x;   // over NMAT/8
    const int which = blockIdx.y;
    const float* Y  = (which == 0) ? Yq : Yk;
    const float* g  = (which == 0) ? gq : gk;
    const float* be = (which == 0) ? betaq : betak;
    uint16_t* H = (which == 0) ? QH : KH;
    uint16_t* L = (which == 0) ? QL : KL;
    const int so = which * CH;
    const int c = (int)((i >> 6) & 511);
    const float inv_n = 1.0f / (float)(BATCH * LSEQ);
    const float m  = g_sum[so + c] * inv_n;
    const float rs = rsqrtf(g_sq[so + c] * inv_n - m * m + EPS);
    const float sc = rs * g[c];
    const float sh = be[c] - m * sc;
    float4 v0 = ((const float4*)Y)[2 * i];
    float4 v1 = ((const float4*)Y)[2 * i + 1];
    v0.x = fmaxf(fmaf(v0.x, sc, sh), 0.f);
    v0.y = fmaxf(fmaf(v0.y, sc, sh), 0.f);
    v0.z = fmaxf(fmaf(v0.z, sc, sh), 0.f);
    v0.w = fmaxf(fmaf(v0.w, sc, sh), 0.f);
    v1.x = fmaxf(fmaf(v1.x, sc, sh), 0.f);
    v1.y = fmaxf(fmaf(v1.y, sc, sh), 0.f);
    v1.z = fmaxf(fmaf(v1.z, sc, sh), 0.f);
    v1.w = fmaxf(fmaf(v1.w, sc, sh), 0.f);
    uint4 h, l;
    h.x = packbf(v0.x, v0.y); h.y = packbf(v0.z, v0.w);
    h.z = packbf(v1.x, v1.y); h.w = packbf(v1.z, v1.w);
    l.x = packbf(v0.x - bf16rt(v0.x), v0.y - bf16rt(v0.y));
    l.y = packbf(v0.z - bf16rt(v0.z), v0.w - bf16rt(v0.w));
    l.z = packbf(v1.x - bf16rt(v1.x), v1.y - bf16rt(v1.y));
    l.w = packbf(v1.z - bf16rt(v1.z), v1.w - bf16rt(v1.w));
    ((uint4*)H)[i] = h;
    ((uint4*)L)[i] = l;
}

// BN+ReLU+split for V (col layout), 8 elems/thread, inline finalize
__global__ __launch_bounds__(128) void bnv_split8(
    const float* __restrict__ Yv,
    const float* __restrict__ gv, const float* __restrict__ betav,
    uint16_t* __restrict__ VH, uint16_t* __restrict__ VL)
{
    const size_t i = (size_t)blockIdx.x * blockDim.x + threadIdx.x;
    const int c8 = (int)(i & 63);
    const float inv_n = 1.0f / (float)(BATCH * LSEQ);
    float4 v0 = ((const float4*)Yv)[2 * i];
    float4 v1 = ((const float4*)Yv)[2 * i + 1];
    float4 g0 = ((const float4*)gv)[2 * c8];
    float4 g1 = ((const float4*)gv)[2 * c8 + 1];
    float4 b0 = ((const float4*)betav)[2 * c8];
    float4 b1 = ((const float4*)betav)[2 * c8 + 1];
    float4 s0 = *(const float4*)(g_sum + 2 * CH + c8 * 8);
    float4 s1 = *(const float4*)(g_sum + 2 * CH + c8 * 8 + 4);
    float4 q0 = *(const float4*)(g_sq  + 2 * CH + c8 * 8);
    float4 q1 = *(const float4*)(g_sq  + 2 * CH + c8 * 8 + 4);
    float m, rs;
#define BNV1(vv, ss, qq, gg, bb) \
    m = (ss) * inv_n; rs = rsqrtf((qq) * inv_n - m * m + EPS); \
    vv = fmaxf(fmaf(vv, rs * (gg), (bb) - m * rs * (gg)), 0.f);
    BNV1(v0.x, s0.x, q0.x, g0.x, b0.x)
    BNV1(v0.y, s0.y, q0.y, g0.y, b0.y)
    BNV1(v0.z, s0.z, q0.z, g0.z, b0.z)
    BNV1(v0.w, s0.w, q0.w, g0.w, b0.w)
    BNV1(v1.x, s1.x, q1.x, g1.x, b1.x)
    BNV1(v1.y, s1.y, q1.y, g1.y, b1.y)
    BNV1(v1.z, s1.z, q1.z, g1.z, b1.z)
    BNV1(v1.w, s1.w, q1.w, g1.w, b1.w)
#undef BNV1
    uint4 h, l;
    h.x = packbf(v0.x, v0.y); h.y = packbf(v0.z, v0.w);
    h.z = packbf(v1.x, v1.y); h.w = packbf(v1.z, v1.w);
    l.x = packbf(v0.x - bf16rt(v0.x), v0.y - bf16rt(v0.y));
    l.y = packbf(v0.z - bf16rt(v0.z), v0.w - bf16rt(v0.w));
    l.z = packbf(v1.x - bf16rt(v1.x), v1.y - bf16rt(v1.y));
    l.w = packbf(v1.z - bf16rt(v1.z), v1.w - bf16rt(v1.w));
    ((uint4*)VH)[i] = h;
    ((uint4*)VL)[i] = l;
}

// softmax over batch axis, half-slice; slice 0 also zeroes stats for next depth
__global__ void softmax_zero(const float* __restrict__ W,
                             uint16_t* __restrict__ H, uint16_t* __restrict__ L,
                             int blockOff)
{
    if (blockOff == 0 && blockIdx.x < 6) {
        const int z = blockIdx.x * 256 + threadIdx.x;
        g_sum[z] = 0.f; g_sq[z] = 0.f;
    }
    const int cd = (blockIdx.x + blockOff) * blockDim.x + threadIdx.x;
    float v[BATCH];
    float mx = -3.402823e38f;
#pragma unroll
    for (int b = 0; b < BATCH; b++) {
        v[b] = W[(size_t)b * MAT + cd];
        mx = fmaxf(mx, v[b]);
    }
    float s = 0.f;
#pragma unroll
    for (int b = 0; b < BATCH; b++) { v[b] = __expf(v[b] - mx); s += v[b]; }
    const float r = 1.0f / s;
#pragma unroll
    for (int b = 0; b < BATCH; b++) {
        const float z = v[b] * r;
        const float h = bf16rt(z);
        __nv_bfloat16 hb = __float2bfloat16(z);
        __nv_bfloat16 lb = __float2bfloat16(z - h);
        H[(size_t)b * MAT + cd] = *reinterpret_cast<uint16_t*>(&hb);
        L[(size_t)b * MAT + cd] = *reinterpret_cast<uint16_t*>(&lb);
    }
}

// ---------------- orchestration -------------------------------------------------
extern "C" void kernel_launch(void* const* d_in, const int* /*in_sizes*/, int /*n_in*/,
                              void* d_out, int /*out_size*/)
{
    const float* P     = (const float*)d_in[0];
    const float* Wq    = (const float*)d_in[1];
    const float* bq    = (const float*)d_in[2];
    const float* gq    = (const float*)d_in[3];
    const float* betaq = (const float*)d_in[4];
    const float* Wk    = (const float*)d_in[5];
    const float* bk    = (const float*)d_in[6];
    const float* gk    = (const float*)d_in[7];
    const float* betak = (const float*)d_in[8];
    const float* Wv    = (const float*)d_in[9];
    const float* bv    = (const float*)d_in[10];
    const float* gv    = (const float*)d_in[11];
    const float* betav = (const float*)d_in[12];

    cudaFuncSetAttribute(gemm_bf3,    cudaFuncAttributeMaxDynamicSharedMemorySize, SMEM_DYN);
    cudaFuncSetAttribute(projQK_gemm, cudaFuncAttributeMaxDynamicSharedMemorySize, SMEM_DYN);
    cudaFuncSetAttribute(projV_gemm,  cudaFuncAttributeMaxDynamicSharedMemorySize, SMEM_DYN);

    float *Y, *Wsc, *sum, *sq;
    uint16_t *bf, *wth, *wtl;
    cudaGetSymbolAddress((void**)&Y,   g_Y);
    cudaGetSymbolAddress((void**)&Wsc, g_Wsc);
    cudaGetSymbolAddress((void**)&bf,  g_bf);
    cudaGetSymbolAddress((void**)&wth, g_wth);
    cudaGetSymbolAddress((void**)&wtl, g_wtl);
    cudaGetSymbolAddress((void**)&sum, g_sum);
    cudaGetSymbolAddress((void**)&sq,  g_sq);

    uint16_t* QH  = bf;
    uint16_t* QL  = bf + 1ULL * NMAT;
    uint16_t* KH  = bf + 2ULL * NMAT;
    uint16_t* KL  = bf + 3ULL * NMAT;
    uint16_t* VH  = bf + 4ULL * NMAT;
    uint16_t* VL  = bf + 5ULL * NMAT;
    uint16_t* WH  = bf + 6ULL * NMAT;
    uint16_t* WL  = bf + 7ULL * NMAT;
    uint16_t* X0H = bf + 8ULL * NMAT;
    uint16_t* X0L = bf + 9ULL * NMAT;
    uint16_t* X1H = bf + 10ULL * NMAT;
    uint16_t* X1L = bf + 11ULL * NMAT;

    float* Yq = Y;
    float* Yk = Y + 1ULL * NMAT;
    float* Yv = Y + 2ULL * NMAT;

    cudaStream_t s2;
    cudaStreamCreateWithFlags(&s2, cudaStreamNonBlocking);
    cudaEvent_t e0, e1;
    cudaEvent_t evQK[3], evP[3], evBN[3], evV[3], evS[3], evSmB[3];
    cudaEventCreateWithFlags(&e0, cudaEventDisableTiming);
    cudaEventCreateWithFlags(&e1, cudaEventDisableTiming);
    for (int d = 0; d < 3; d++) {
        cudaEventCreateWithFlags(&evQK[d],  cudaEventDisableTiming);
        cudaEventCreateWithFlags(&evP[d],   cudaEventDisableTiming);
        cudaEventCreateWithFlags(&evBN[d],  cudaEventDisableTiming);
        cudaEventCreateWithFlags(&evV[d],   cudaEventDisableTiming);
        cudaEventCreateWithFlags(&evS[d],   cudaEventDisableTiming);
        cudaEventCreateWithFlags(&evSmB[d], cudaEventDisableTiming);
    }

    // prologue: weights+stats on s2, transpose on main, join
    cudaEventRecord(e0, 0);
    cudaStreamWaitEvent(s2, e0, 0);
    cvt_split3<<<dim3(3 * MAT / 8 / 256, 3), 256, 0, s2>>>(Wq, Wk, Wv, wth, wtl);
    zero_stats<<<6, 256, 0, s2>>>();
    cudaEventRecord(e1, s2);
    transpose_split<<<dim3(16, 16, BATCH), dim3(32, 8)>>>(P, X0H, X0L);
    cudaStreamWaitEvent(0, e1, 0);

    for (int d = 0; d < 3; d++) {
        uint16_t* XiH = (d == 1) ? X1H : X0H;
        uint16_t* XiL = (d == 1) ? X1L : X0L;
        uint16_t* XoH = (d == 0) ? X1H : X0H;
        uint16_t* XoL = (d == 0) ? X1L : X0L;

        const uint16_t* wqh = wth + (0ULL * 3 + d) * MAT;
        const uint16_t* wql = wtl + (0ULL * 3 + d) * MAT;
        const uint16_t* wkh = wth + (1ULL * 3 + d) * MAT;
        const uint16_t* wkl = wtl + (1ULL * 3 + d) * MAT;
        const uint16_t* wvh = wth + (2ULL * 3 + d) * MAT;
        const uint16_t* wvl = wtl + (2ULL * 3 + d) * MAT;

        // main: Q+K projections, then V projection
        projQK_gemm<<<dim3(4, 4, 2 * BATCH), 128, SMEM_DYN>>>(
            wqh, wql, wkh, wkl, XiH, XiL, Yq, Yk,
            bq + d * CH, bk + d * CH, sum, sq);
        cudaEventRecord(evQK[d], 0);
        projV_gemm<<<dim3(4, 4, BATCH), 128, SMEM_DYN>>>(
            XiH, XiL, wvh, wvl, Yv, bv + d * CH, sum + 2 * CH, sq + 2 * CH);
        cudaEventRecord(evP[d], 0);

        // s2: bnqk under projV; bnv next
        cudaStreamWaitEvent(s2, evQK[d], 0);
        bnqk_split8<<<dim3(NMAT / 8 / 256, 2), 256, 0, s2>>>(
            Yq, Yk, gq + d * CH, betaq + d * CH, gk + d * CH, betak + d * CH,
            QH, QL, KH, KL);
        cudaEventRecord(evBN[d], s2);
        cudaStreamWaitEvent(s2, evP[d], 0);
        bnv_split8<<<NMAT / 8 / 128, 128, 0, s2>>>(Yv, gv + d * CH, betav + d * CH, VH, VL);
        cudaEventRecord(evV[d], s2);

        // main: scores (single launch), then softmax half A (+stat zero)
        cudaStreamWaitEvent(0, evBN[d], 0);
        gemm_bf3<<<dim3(4, 4, BATCH), 128, SMEM_DYN>>>(QH, QL, MAT, KH, KL, MAT,
                                                       Wsc, nullptr, nullptr, 0);
        cudaEventRecord(evS[d], 0);
        cudaStreamWaitEvent(0, evV[d], 0);      // stat readers done before zeroing
        softmax_zero<<<MAT / 256 / 2, 256>>>(Wsc, WH, WL, 0);

        // s2: softmax half B (in-order after bnv; waits scores)
        cudaStreamWaitEvent(s2, evS[d], 0);
        softmax_zero<<<MAT / 256 / 2, 256, 0, s2>>>(Wsc, WH, WL, MAT / 256 / 2);
        cudaEventRecord(evSmB[d], s2);

        // main: AV (single launch) after both softmax halves
        cudaStreamWaitEvent(0, evSmB[d], 0);
        if (d < 2) {
            gemm_bf3<<<dim3(4, 4, BATCH), 128, SMEM_DYN>>>(VH, VL, MAT, WH, WL, MAT,
                                                           nullptr, XoH, XoL, 3);
        } else {
            gemm_bf3<<<dim3(4, 4, BATCH), 128, SMEM_DYN>>>(WH, WL, MAT, VH, VL, MAT,
                                                           (float*)d_out, nullptr, nullptr, 0);
        }
    }
}

// round 15
// speedup vs baseline: 1.0148x; 1.0148x over previous
#include <cuda_runtime.h>
#include <cuda_bf16.h>
#include <cstdint>
#include <cstddef>

#define BATCH 64
#define CH    512
#define LSEQ  512
#define MAT   (CH * LSEQ)
#define NMAT  (BATCH * MAT)
#define EPS   1e-5f

// ---------------- scratch -----------------------------------------------------
__device__ float    g_Y[3ULL * NMAT];        // Q,K,VT pre-BN fp32
__device__ float    g_Wsc[NMAT];             // scores fp32
__device__ uint16_t g_bf[12ULL * NMAT];      // QH,QL,KH,KL,VH,VL,WH,WL,X0H,X0L,X1H,X1L
__device__ uint16_t g_wth[9ULL * MAT];
__device__ uint16_t g_wtl[9ULL * MAT];
__device__ float g_sum[3 * CH];
__device__ float g_sq[3 * CH];

// ---------------- helpers ------------------------------------------------------
__device__ __forceinline__ uint32_t packbf(float a, float b) {
    __nv_bfloat162 t = __floats2bfloat162_rn(a, b);
    return *reinterpret_cast<uint32_t*>(&t);
}
__device__ __forceinline__ float bf16rt(float x) {
    return __bfloat162float(__float2bfloat16(x));
}

#define LDSM4(R, addr) \
    asm volatile("ldmatrix.sync.aligned.m8n8.x4.shared.b16 {%0,%1,%2,%3}, [%4];" \
        : "=r"((R)[0]), "=r"((R)[1]), "=r"((R)[2]), "=r"((R)[3]) : "r"(addr))

__device__ __forceinline__ void mma16816(float* d, const uint32_t* a,
                                         uint32_t b0, uint32_t b1) {
    asm volatile(
        "mma.sync.aligned.m16n8k16.row.col.f32.bf16.bf16.f32 "
        "{%0,%1,%2,%3}, {%4,%5,%6,%7}, {%8,%9}, {%0,%1,%2,%3};"
        : "+f"(d[0]), "+f"(d[1]), "+f"(d[2]), "+f"(d[3])
        : "r"(a[0]), "r"(a[1]), "r"(a[2]), "r"(a[3]), "r"(b0), "r"(b1));
}

#define CP16(dst, src) \
    asm volatile("cp.async.cg.shared.global [%0], [%1], 16;" :: "r"(dst), "l"(src))
#define CPCOMMIT() asm volatile("cp.async.commit_group;" ::: "memory")
#define CPWAIT1()  asm volatile("cp.async.wait_group 1;" ::: "memory")

// ---------------- GEMM core (NT, bf16x3, pre-split operands) -------------------
#define KC 32
#define TILE_B  8192
#define STAGE_B 32768
#define SMEM_DYN (3 * STAGE_B)

__device__ __forceinline__ void gemm_core(
    const uint16_t* __restrict__ Ah, const uint16_t* __restrict__ Al,
    const uint16_t* __restrict__ Bh, const uint16_t* __restrict__ Bl,
    float* __restrict__ CfB, uint16_t* __restrict__ ChB, uint16_t* __restrict__ ClB,
    const float* __restrict__ bias,
    float* __restrict__ sums, float* __restrict__ sqs,
    int m0, int n0, int outMode)
{
    extern __shared__ uint8_t smraw[];
    const uint32_t smemu = (uint32_t)__cvta_generic_to_shared(smraw);
    const int tid  = threadIdx.x;
    const int lane = tid & 31, wid = tid >> 5;

    const int r0 = tid >> 2, k0 = tid & 3;
    const uint32_t dst0 = (uint32_t)(r0 * 64 + ((k0 ^ ((r0 >> 1) & 3)) << 4));
    const char* aH0 = (const char*)(Ah + (size_t)(m0 + r0) * 512 + k0 * 8);
    const char* aL0 = (const char*)(Al + (size_t)(m0 + r0) * 512 + k0 * 8);
    const char* bH0 = (const char*)(Bh + (size_t)(n0 + r0) * 512 + k0 * 8);
    const char* bL0 = (const char*)(Bl + (size_t)(n0 + r0) * 512 + k0 * 8);

    auto issue = [&](int s, int c) {
        const uint32_t sb = smemu + (uint32_t)s * STAGE_B;
        const size_t o = (size_t)c * (KC * 2);
#pragma unroll
        for (int p = 0; p < 4; p++) {
            const uint32_t d = sb + dst0 + p * 2048;
            const size_t so = o + (size_t)p * 32768;
            CP16(d,              aH0 + so);
            CP16(d + TILE_B,     aL0 + so);
            CP16(d + 2 * TILE_B, bH0 + so);
            CP16(d + 3 * TILE_B, bL0 + so);
        }
    };

    const int mw = (wid & 1) * 64;
    const int nw = (wid >> 1) * 64;
    const int lrow = (lane & 7) + 8 * ((lane >> 3) & 1);
    const int lk16 = lane >> 4;
    uint32_t offA[4][2], offB[4][2];
#pragma unroll
    for (int fi = 0; fi < 4; fi++) {
        const int row = mw + fi * 16 + lrow;
        const uint32_t sw = (row >> 1) & 3;
        offA[fi][0] = (uint32_t)(row * 64 + (((0 + lk16) ^ sw) << 4));
        offA[fi][1] = (uint32_t)(row * 64 + (((2 + lk16) ^ sw) << 4));
    }
#pragma unroll
    for (int bj = 0; bj < 4; bj++) {
        const int row = nw + bj * 16 + lrow;
        const uint32_t sw = (row >> 1) & 3;
        offB[bj][0] = (uint32_t)(row * 64 + (((0 + lk16) ^ sw) << 4));
        offB[bj][1] = (uint32_t)(row * 64 + (((2 + lk16) ^ sw) << 4));
    }

    float acc[4][8][4];
#pragma unroll
    for (int i = 0; i < 4; i++)
#pragma unroll
        for (int j = 0; j < 8; j++)
#pragma unroll
            for (int e = 0; e < 4; e++) acc[i][j][e] = 0.f;

    auto compute = [&](int s) {
        const uint32_t sb = smemu + (uint32_t)s * STAGE_B;
#pragma unroll
        for (int kg = 0; kg < 2; kg++) {
            uint32_t Ahr[4][4], Bhr[4][4], Blr[4][4], Alr[4][4];
#pragma unroll
            for (int fi = 0; fi < 4; fi++)
                LDSM4(Ahr[fi], sb + offA[fi][kg]);
#pragma unroll
            for (int bj = 0; bj < 4; bj++)
                LDSM4(Bhr[bj], sb + 2 * TILE_B + offB[bj][kg]);
#pragma unroll
            for (int i = 0; i < 4; i++)
#pragma unroll
                for (int j = 0; j < 8; j++)
                    mma16816(acc[i][j], Ahr[i], Bhr[j >> 1][j & 1], Bhr[j >> 1][(j & 1) + 2]);
#pragma unroll
            for (int bj = 0; bj < 4; bj++)
                LDSM4(Blr[bj], sb + 3 * TILE_B + offB[bj][kg]);
#pragma unroll
            for (int i = 0; i < 4; i++)
#pragma unroll
                for (int j = 0; j < 8; j++)
                    mma16816(acc[i][j], Ahr[i], Blr[j >> 1][j & 1], Blr[j >> 1][(j & 1) + 2]);
#pragma unroll
            for (int fi = 0; fi < 4; fi++)
                LDSM4(Alr[fi], sb + TILE_B + offA[fi][kg]);
#pragma unroll
            for (int i = 0; i < 4; i++)
#pragma unroll
                for (int j = 0; j < 8; j++)
                    mma16816(acc[i][j], Alr[i], Bhr[j >> 1][j & 1], Bhr[j >> 1][(j & 1) + 2]);
        }
    };

    issue(0, 0); CPCOMMIT();
    issue(1, 1); CPCOMMIT();

#pragma unroll 1
    for (int c = 0; c < 16; c++) {
        CPWAIT1();
        __syncthreads();
        if (c + 2 < 16) issue((c + 2) % 3, c + 2);
        CPCOMMIT();
        compute(c % 3);
    }

    // ---------------- epilogue ----------------
    const int rg = lane >> 2;
    const int cg = (lane & 3) * 2;

    float bc[16], cs[16], cq[16];
    if (outMode == 2) {
#pragma unroll
        for (int j = 0; j < 8; j++) {
            bc[2 * j]     = bias[n0 + nw + j * 8 + cg];
            bc[2 * j + 1] = bias[n0 + nw + j * 8 + cg + 1];
        }
#pragma unroll
        for (int e = 0; e < 16; e++) { cs[e] = 0.f; cq[e] = 0.f; }
    }

#pragma unroll
    for (int i = 0; i < 4; i++) {
        const int row0 = m0 + mw + i * 16 + rg;
        const int row1 = row0 + 8;
        float bv0 = 0.f, bv1 = 0.f;
        if (outMode == 1) { bv0 = bias[row0]; bv1 = bias[row1]; }
        float s0 = 0.f, q0 = 0.f, s1 = 0.f, q1 = 0.f;
#pragma unroll
        for (int j = 0; j < 8; j++) {
            float* cc = acc[i][j];
            if (outMode == 1) { cc[0] += bv0; cc[1] += bv0; cc[2] += bv1; cc[3] += bv1; }
            if (outMode == 2) {
                cc[0] += bc[2 * j]; cc[1] += bc[2 * j + 1];
                cc[2] += bc[2 * j]; cc[3] += bc[2 * j + 1];
            }
            const int col = n0 + nw + j * 8 + cg;
            if (outMode == 3) {
                uint32_t* H = (uint32_t*)ChB;
                uint32_t* L = (uint32_t*)ClB;
                const size_t i0 = ((size_t)row0 * 512 + col) >> 1;
                const size_t i1 = ((size_t)row1 * 512 + col) >> 1;
                H[i0] = packbf(cc[0], cc[1]);
                L[i0] = packbf(cc[0] - bf16rt(cc[0]), cc[1] - bf16rt(cc[1]));
                H[i1] = packbf(cc[2], cc[3]);
                L[i1] = packbf(cc[2] - bf16rt(cc[2]), cc[3] - bf16rt(cc[3]));
            } else {
                *(float2*)&CfB[(size_t)row0 * 512 + col] = make_float2(cc[0], cc[1]);
                *(float2*)&CfB[(size_t)row1 * 512 + col] = make_float2(cc[2], cc[3]);
            }
            if (outMode == 1) {
                s0 += cc[0] + cc[1]; q0 += cc[0] * cc[0] + cc[1] * cc[1];
                s1 += cc[2] + cc[3]; q1 += cc[2] * cc[2] + cc[3] * cc[3];
            }
            if (outMode == 2) {
                cs[2 * j]     += cc[0] + cc[2];
                cs[2 * j + 1] += cc[1] + cc[3];
                cq[2 * j]     += cc[0] * cc[0] + cc[2] * cc[2];
                cq[2 * j + 1] += cc[1] * cc[1] + cc[3] * cc[3];
            }
        }
        if (outMode == 1) {
#pragma unroll
            for (int off = 1; off <= 2; off <<= 1) {
                s0 += __shfl_xor_sync(0xffffffffu, s0, off);
                q0 += __shfl_xor_sync(0xffffffffu, q0, off);
                s1 += __shfl_xor_sync(0xffffffffu, s1, off);
                q1 += __shfl_xor_sync(0xffffffffu, q1, off);
            }
            if ((lane & 3) == 0) {
                atomicAdd(&sums[row0], s0); atomicAdd(&sqs[row0], q0);
                atomicAdd(&sums[row1], s1); atomicAdd(&sqs[row1], q1);
            }
        }
    }
    if (outMode == 2) {
#pragma unroll
        for (int e = 0; e < 16; e++) {
#pragma unroll
            for (int off = 4; off <= 16; off <<= 1) {
                cs[e] += __shfl_xor_sync(0xffffffffu, cs[e], off);
                cq[e] += __shfl_xor_sync(0xffffffffu, cq[e], off);
            }
        }
        if (rg == 0) {
#pragma unroll
            for (int j = 0; j < 8; j++) {
                const int col = n0 + nw + j * 8 + cg;
                atomicAdd(&sums[col], cs[2 * j]);         atomicAdd(&sqs[col], cq[2 * j]);
                atomicAdd(&sums[col + 1], cs[2 * j + 1]); atomicAdd(&sqs[col + 1], cq[2 * j + 1]);
            }
        }
    }
}

// standalone GEMM with tile offsets (scores / AV slices)
__global__ __launch_bounds__(128, 2) void gemm_bf3(
    const uint16_t* __restrict__ Ah, const uint16_t* __restrict__ Al, int strideA,
    const uint16_t* __restrict__ Bh, const uint16_t* __restrict__ Bl, int strideB,
    float* __restrict__ Cf,
    uint16_t* __restrict__ Ch, uint16_t* __restrict__ Cl,
    int outMode, int xoff, int yoff, int zoff)
{
    const int b = blockIdx.z + zoff;
    gemm_core(Ah + (size_t)b * strideA, Al + (size_t)b * strideA,
              Bh + (size_t)b * strideB, Bl + (size_t)b * strideB,
              Cf ? Cf + (size_t)b * MAT : nullptr,
              Ch ? Ch + (size_t)b * MAT : nullptr,
              Cl ? Cl + (size_t)b * MAT : nullptr,
              nullptr, nullptr, nullptr,
              (blockIdx.y + yoff) * 128, (blockIdx.x + xoff) * 128, outMode);
}

// fused Q+K projection GEMM: z in [0,128), proj = z>>6, batch = z&63  (mode 1)
__global__ __launch_bounds__(128, 2) void projQK_gemm(
    const uint16_t* __restrict__ wqh, const uint16_t* __restrict__ wql,
    const uint16_t* __restrict__ wkh, const uint16_t* __restrict__ wkl,
    const uint16_t* __restrict__ XiH, const uint16_t* __restrict__ XiL,
    float* __restrict__ Yq, float* __restrict__ Yk,
    const float* __restrict__ bq, const float* __restrict__ bk,
    float* __restrict__ sum, float* __restrict__ sq)
{
    const int proj = blockIdx.z >> 6;
    const int b    = blockIdx.z & 63;
    const size_t xo = (size_t)b * MAT;
    if (proj == 0)
        gemm_core(wqh, wql, XiH + xo, XiL + xo, Yq + xo, nullptr, nullptr,
                  bq, sum, sq, blockIdx.y * 128, blockIdx.x * 128, 1);
    else
        gemm_core(wkh, wkl, XiH + xo, XiL + xo, Yk + xo, nullptr, nullptr,
                  bk, sum + CH, sq + CH, blockIdx.y * 128, blockIdx.x * 128, 1);
}

// V projection GEMM (mode 2, col-stats)
__global__ __launch_bounds__(128, 2) void projV_gemm(
    const uint16_t* __restrict__ XiH, const uint16_t* __restrict__ XiL,
    const uint16_t* __restrict__ wvh, const uint16_t* __restrict__ wvl,
    float* __restrict__ Yv, const float* __restrict__ bv,
    float* __restrict__ sums, float* __restrict__ sqs)
{
    const size_t xo = (size_t)blockIdx.z * MAT;
    gemm_core(XiH + xo, XiL + xo, wvh, wvl, Yv + xo, nullptr, nullptr,
              bv, sums, sqs, blockIdx.y * 128, blockIdx.x * 128, 2);
}

// ---------------- elementwise kernels -------------------------------------------
__global__ void transpose_split(const float* __restrict__ src,
                                uint16_t* __restrict__ H, uint16_t* __restrict__ L)
{
    __shared__ float t[32][33];
    const int b = blockIdx.z;
    const int x0 = blockIdx.x * 32;
    const int y0 = blockIdx.y * 32;
    const float* S = src + (size_t)b * MAT;
    const int tx = threadIdx.x, ty = threadIdx.y;
#pragma unroll
    for (int j = 0; j < 32; j += 8)
        t[ty + j][tx] = S[(size_t)(y0 + ty + j) * 512 + x0 + tx];
    __syncthreads();
    uint16_t* Hb = H + (size_t)b * MAT;
    uint16_t* Lb = L + (size_t)b * MAT;
#pragma unroll
    for (int j = 0; j < 32; j += 8) {
        float v = t[tx][ty + j];
        float h = bf16rt(v);
        const size_t idx = (size_t)(x0 + ty + j) * 512 + y0 + tx;
        __nv_bfloat16 hb = __float2bfloat16(v);
        __nv_bfloat16 lb = __float2bfloat16(v - h);
        Hb[idx] = *reinterpret_cast<uint16_t*>(&hb);
        Lb[idx] = *reinterpret_cast<uint16_t*>(&lb);
    }
}

__global__ void cvt_split3(const float* __restrict__ Wq, const float* __restrict__ Wk,
                           const float* __restrict__ Wv,
                           uint16_t* __restrict__ Hall, uint16_t* __restrict__ Lall)
{
    const int w = blockIdx.y;
    const float* src = (w == 0) ? Wq : (w == 1) ? Wk : Wv;
    uint16_t* H = Hall + (size_t)w * 3 * MAT;
    uint16_t* L = Lall + (size_t)w * 3 * MAT;
    const size_t i = (size_t)blockIdx.x * blockDim.x + threadIdx.x;
    float4 v0 = ((const float4*)src)[2 * i];
    float4 v1 = ((const float4*)src)[2 * i + 1];
    uint4 h, l;
    h.x = packbf(v0.x, v0.y); h.y = packbf(v0.z, v0.w);
    h.z = packbf(v1.x, v1.y); h.w = packbf(v1.z, v1.w);
    l.x = packbf(v0.x - bf16rt(v0.x), v0.y - bf16rt(v0.y));
    l.y = packbf(v0.z - bf16rt(v0.z), v0.w - bf16rt(v0.w));
    l.z = packbf(v1.x - bf16rt(v1.x), v1.y - bf16rt(v1.y));
    l.w = packbf(v1.z - bf16rt(v1.z), v1.w - bf16rt(v1.w));
    ((uint4*)H)[i] = h;
    ((uint4*)L)[i] = l;
}

__global__ void zero_stats()
{
    int i = blockIdx.x * blockDim.x + threadIdx.x;
    if (i < 3 * CH) { g_sum[i] = 0.f; g_sq[i] = 0.f; }
}

// BN+ReLU+split for Q,K (row layout), 8 elems/thread, inline finalize; y selects Q/K
__global__ void bnqk_split8(
    const float* __restrict__ Yq, const float* __restrict__ Yk,
    const float* __restrict__ gq, const float* __restrict__ betaq,
    const float* __restrict__ gk, const float* __restrict__ betak,
    uint16_t* __restrict__ QH, uint16_t* __restrict__ QL,
    uint16_t* __restrict__ KH, uint16_t* __restrict__ KL)
{
    const size_t i = (size_t)blockIdx.x * blockDim.x + threadIdx.x;   // over NMAT/8
    const int which = blockIdx.y;
    const float* Y  = (which == 0) ? Yq : Yk;
    const float* g  = (which == 0) ? gq : gk;
    const float* be = (which == 0) ? betaq : betak;
    uint16_t* H = (which == 0) ? QH : KH;
    uint16_t* L = (which == 0) ? QL : KL;
    const int so = which * CH;
    const int c = (int)((i >> 6) & 511);
    const float inv_n = 1.0f / (float)(BATCH * LSEQ);
    const float m  = g_sum[so + c] * inv_n;
    const float rs = rsqrtf(g_sq[so + c] * inv_n - m * m + EPS);
    const float sc = rs * g[c];
    const float sh = be[c] - m * sc;
    float4 v0 = ((const float4*)Y)[2 * i];
    float4 v1 = ((const float4*)Y)[2 * i + 1];
    v0.x = fmaxf(fmaf(v0.x, sc, sh), 0.f);
    v0.y = fmaxf(fmaf(v0.y, sc, sh), 0.f);
    v0.z = fmaxf(fmaf(v0.z, sc, sh), 0.f);
    v0.w = fmaxf(fmaf(v0.w, sc, sh), 0.f);
    v1.x = fmaxf(fmaf(v1.x, sc, sh), 0.f);
    v1.y = fmaxf(fmaf(v1.y, sc, sh), 0.f);
    v1.z = fmaxf(fmaf(v1.z, sc, sh), 0.f);
    v1.w = fmaxf(fmaf(v1.w, sc, sh), 0.f);
    uint4 h, l;
    h.x = packbf(v0.x, v0.y); h.y = packbf(v0.z, v0.w);
    h.z = packbf(v1.x, v1.y); h.w = packbf(v1.z, v1.w);
    l.x = packbf(v0.x - bf16rt(v0.x), v0.y - bf16rt(v0.y));
    l.y = packbf(v0.z - bf16rt(v0.z), v0.w - bf16rt(v0.w));
    l.z = packbf(v1.x - bf16rt(v1.x), v1.y - bf16rt(v1.y));
    l.w = packbf(v1.z - bf16rt(v1.z), v1.w - bf16rt(v1.w));
    ((uint4*)H)[i] = h;
    ((uint4*)L)[i] = l;
}

// BN+ReLU+split for V (col layout), 8 elems/thread, inline finalize
__global__ __launch_bounds__(128) void bnv_split8(
    const float* __restrict__ Yv,
    const float* __restrict__ gv, const float* __restrict__ betav,
    uint16_t* __restrict__ VH, uint16_t* __restrict__ VL)
{
    const size_t i = (size_t)blockIdx.x * blockDim.x + threadIdx.x;
    const int c8 = (int)(i & 63);
    const float inv_n = 1.0f / (float)(BATCH * LSEQ);
    float4 v0 = ((const float4*)Yv)[2 * i];
    float4 v1 = ((const float4*)Yv)[2 * i + 1];
    float4 g0 = ((const float4*)gv)[2 * c8];
    float4 g1 = ((const float4*)gv)[2 * c8 + 1];
    float4 b0 = ((const float4*)betav)[2 * c8];
    float4 b1 = ((const float4*)betav)[2 * c8 + 1];
    float4 s0 = *(const float4*)(g_sum + 2 * CH + c8 * 8);
    float4 s1 = *(const float4*)(g_sum + 2 * CH + c8 * 8 + 4);
    float4 q0 = *(const float4*)(g_sq  + 2 * CH + c8 * 8);
    float4 q1 = *(const float4*)(g_sq  + 2 * CH + c8 * 8 + 4);
    float m, rs;
#define BNV1(vv, ss, qq, gg, bb) \
    m = (ss) * inv_n; rs = rsqrtf((qq) * inv_n - m * m + EPS); \
    vv = fmaxf(fmaf(vv, rs * (gg), (bb) - m * rs * (gg)), 0.f);
    BNV1(v0.x, s0.x, q0.x, g0.x, b0.x)
    BNV1(v0.y, s0.y, q0.y, g0.y, b0.y)
    BNV1(v0.z, s0.z, q0.z, g0.z, b0.z)
    BNV1(v0.w, s0.w, q0.w, g0.w, b0.w)
    BNV1(v1.x, s1.x, q1.x, g1.x, b1.x)
    BNV1(v1.y, s1.y, q1.y, g1.y, b1.y)
    BNV1(v1.z, s1.z, q1.z, g1.z, b1.z)
    BNV1(v1.w, s1.w, q1.w, g1.w, b1.w)
#undef BNV1
    uint4 h, l;
    h.x = packbf(v0.x, v0.y); h.y = packbf(v0.z, v0.w);
    h.z = packbf(v1.x, v1.y); h.w = packbf(v1.z, v1.w);
    l.x = packbf(v0.x - bf16rt(v0.x), v0.y - bf16rt(v0.y));
    l.y = packbf(v0.z - bf16rt(v0.z), v0.w - bf16rt(v0.w));
    l.z = packbf(v1.x - bf16rt(v1.x), v1.y - bf16rt(v1.y));
    l.w = packbf(v1.z - bf16rt(v1.z), v1.w - bf16rt(v1.w));
    ((uint4*)VH)[i] = h;
    ((uint4*)VL)[i] = l;
}

// softmax over batch axis, half-slice; slice 0 also zeroes stats for next depth
__global__ void softmax_zero(const float* __restrict__ W,
                             uint16_t* __restrict__ H, uint16_t* __restrict__ L,
                             int blockOff)
{
    if (blockOff == 0 && blockIdx.x < 6) {
        const int z = blockIdx.x * 256 + threadIdx.x;
        g_sum[z] = 0.f; g_sq[z] = 0.f;
    }
    const int cd = (blockIdx.x + blockOff) * blockDim.x + threadIdx.x;
    float v[BATCH];
    float mx = -3.402823e38f;
#pragma unroll
    for (int b = 0; b < BATCH; b++) {
        v[b] = W[(size_t)b * MAT + cd];
        mx = fmaxf(mx, v[b]);
    }
    float s = 0.f;
#pragma unroll
    for (int b = 0; b < BATCH; b++) { v[b] = __expf(v[b] - mx); s += v[b]; }
    const float r = 1.0f / s;
#pragma unroll
    for (int b = 0; b < BATCH; b++) {
        const float z = v[b] * r;
        const float h = bf16rt(z);
        __nv_bfloat16 hb = __float2bfloat16(z);
        __nv_bfloat16 lb = __float2bfloat16(z - h);
        H[(size_t)b * MAT + cd] = *reinterpret_cast<uint16_t*>(&hb);
        L[(size_t)b * MAT + cd] = *reinterpret_cast<uint16_t*>(&lb);
    }
}

// ---------------- orchestration -------------------------------------------------
extern "C" void kernel_launch(void* const* d_in, const int* /*in_sizes*/, int /*n_in*/,
                              void* d_out, int /*out_size*/)
{
    const float* P     = (const float*)d_in[0];
    const float* Wq    = (const float*)d_in[1];
    const float* bq    = (const float*)d_in[2];
    const float* gq    = (const float*)d_in[3];
    const float* betaq = (const float*)d_in[4];
    const float* Wk    = (const float*)d_in[5];
    const float* bk    = (const float*)d_in[6];
    const float* gk    = (const float*)d_in[7];
    const float* betak = (const float*)d_in[8];
    const float* Wv    = (const float*)d_in[9];
    const float* bv    = (const float*)d_in[10];
    const float* gv    = (const float*)d_in[11];
    const float* betav = (const float*)d_in[12];

    cudaFuncSetAttribute(gemm_bf3,    cudaFuncAttributeMaxDynamicSharedMemorySize, SMEM_DYN);
    cudaFuncSetAttribute(projQK_gemm, cudaFuncAttributeMaxDynamicSharedMemorySize, SMEM_DYN);
    cudaFuncSetAttribute(projV_gemm,  cudaFuncAttributeMaxDynamicSharedMemorySize, SMEM_DYN);

    float *Y, *Wsc, *sum, *sq;
    uint16_t *bf, *wth, *wtl;
    cudaGetSymbolAddress((void**)&Y,   g_Y);
    cudaGetSymbolAddress((void**)&Wsc, g_Wsc);
    cudaGetSymbolAddress((void**)&bf,  g_bf);
    cudaGetSymbolAddress((void**)&wth, g_wth);
    cudaGetSymbolAddress((void**)&wtl, g_wtl);
    cudaGetSymbolAddress((void**)&sum, g_sum);
    cudaGetSymbolAddress((void**)&sq,  g_sq);

    uint16_t* QH  = bf;
    uint16_t* QL  = bf + 1ULL * NMAT;
    uint16_t* KH  = bf + 2ULL * NMAT;
    uint16_t* KL  = bf + 3ULL * NMAT;
    uint16_t* VH  = bf + 4ULL * NMAT;
    uint16_t* VL  = bf + 5ULL * NMAT;
    uint16_t* WH  = bf + 6ULL * NMAT;
    uint16_t* WL  = bf + 7ULL * NMAT;
    uint16_t* X0H = bf + 8ULL * NMAT;
    uint16_t* X0L = bf + 9ULL * NMAT;
    uint16_t* X1H = bf + 10ULL * NMAT;
    uint16_t* X1L = bf + 11ULL * NMAT;

    float* Yq = Y;
    float* Yk = Y + 1ULL * NMAT;
    float* Yv = Y + 2ULL * NMAT;

    cudaStream_t s2;
    cudaStreamCreateWithFlags(&s2, cudaStreamNonBlocking);
    cudaEvent_t e0, e1;
    cudaEvent_t evQK[3], evP[3], evBN[3], evSA[3], evSB[3], evA1[3];
    cudaEventCreateWithFlags(&e0, cudaEventDisableTiming);
    cudaEventCreateWithFlags(&e1, cudaEventDisableTiming);
    for (int d = 0; d < 3; d++) {
        cudaEventCreateWithFlags(&evQK[d], cudaEventDisableTiming);
        cudaEventCreateWithFlags(&evP[d],  cudaEventDisableTiming);
        cudaEventCreateWithFlags(&evBN[d], cudaEventDisableTiming);
        cudaEventCreateWithFlags(&evSA[d], cudaEventDisableTiming);
        cudaEventCreateWithFlags(&evSB[d], cudaEventDisableTiming);
        cudaEventCreateWithFlags(&evA1[d], cudaEventDisableTiming);
    }

    // prologue: weights+stats on s2, transpose on main, join
    cudaEventRecord(e0, 0);
    cudaStreamWaitEvent(s2, e0, 0);
    cvt_split3<<<dim3(3 * MAT / 8 / 256, 3), 256, 0, s2>>>(Wq, Wk, Wv, wth, wtl);
    zero_stats<<<6, 256, 0, s2>>>();
    cudaEventRecord(e1, s2);
    transpose_split<<<dim3(16, 16, BATCH), dim3(32, 8)>>>(P, X0H, X0L);
    cudaStreamWaitEvent(0, e1, 0);

    for (int d = 0; d < 3; d++) {
        uint16_t* XiH = (d == 1) ? X1H : X0H;
        uint16_t* XiL = (d == 1) ? X1L : X0L;
        uint16_t* XoH = (d == 0) ? X1H : X0H;
        uint16_t* XoL = (d == 0) ? X1L : X0L;

        const uint16_t* wqh = wth + (0ULL * 3 + d) * MAT;
        const uint16_t* wql = wtl + (0ULL * 3 + d) * MAT;
        const uint16_t* wkh = wth + (1ULL * 3 + d) * MAT;
        const uint16_t* wkl = wtl + (1ULL * 3 + d) * MAT;
        const uint16_t* wvh = wth + (2ULL * 3 + d) * MAT;
        const uint16_t* wvl = wtl + (2ULL * 3 + d) * MAT;

        // main: Q+K projections, then V projection
        projQK_gemm<<<dim3(4, 4, 2 * BATCH), 128, SMEM_DYN>>>(
            wqh, wql, wkh, wkl, XiH, XiL, Yq, Yk,
            bq + d * CH, bk + d * CH, sum, sq);
        cudaEventRecord(evQK[d], 0);
        projV_gemm<<<dim3(4, 4, BATCH), 128, SMEM_DYN>>>(
            XiH, XiL, wvh, wvl, Yv, bv + d * CH, sum + 2 * CH, sq + 2 * CH);
        cudaEventRecord(evP[d], 0);

        // s2: bnqk under projV; bnv under scoresA
        cudaStreamWaitEvent(s2, evQK[d], 0);
        bnqk_split8<<<dim3(NMAT / 8 / 256, 2), 256, 0, s2>>>(
            Yq, Yk, gq + d * CH, betaq + d * CH, gk + d * CH, betak + d * CH,
            QH, QL, KH, KL);
        cudaEventRecord(evBN[d], s2);
        cudaStreamWaitEvent(s2, evP[d], 0);
        bnv_split8<<<NMAT / 8 / 128, 128, 0, s2>>>(Yv, gv + d * CH, betav + d * CH, VH, VL);

        // scores: main batches 0..31 (after bn), s2 batches 32..63 (in-order after bnv)
        cudaStreamWaitEvent(0, evBN[d], 0);
        gemm_bf3<<<dim3(4, 4, 32), 128, SMEM_DYN>>>(QH, QL, MAT, KH, KL, MAT,
                                                    Wsc, nullptr, nullptr, 0, 0, 0, 0);
        cudaEventRecord(evSA[d], 0);
        gemm_bf3<<<dim3(4, 4, 32), 128, SMEM_DYN, s2>>>(QH, QL, MAT, KH, KL, MAT,
                                                        Wsc, nullptr, nullptr, 0, 0, 0, 32);
        cudaEventRecord(evSB[d], s2);

        // softmax halves (each needs ALL batches of scores)
        cudaStreamWaitEvent(0, evSB[d], 0);
        softmax_zero<<<MAT / 256 / 2, 256>>>(Wsc, WH, WL, 0);               // c < 256 (+ stat zero)
        cudaStreamWaitEvent(s2, evSA[d], 0);
        softmax_zero<<<MAT / 256 / 2, 256, 0, s2>>>(Wsc, WH, WL, MAT / 256 / 2);  // c >= 256

        if (d < 2) {
            // xT_next[l][c] = VT x w ; out cols c -> slice by x
            gemm_bf3<<<dim3(2, 4, 64), 128, SMEM_DYN>>>(VH, VL, MAT, WH, WL, MAT,
                                                        nullptr, XoH, XoL, 3, 0, 0, 0);
            gemm_bf3<<<dim3(2, 4, 64), 128, SMEM_DYN, s2>>>(VH, VL, MAT, WH, WL, MAT,
                                                            nullptr, XoH, XoL, 3, 2, 0, 0);
        } else {
            // out[c][l] = w x VT ; out rows c -> slice by y
            gemm_bf3<<<dim3(4, 2, 64), 128, SMEM_DYN>>>(WH, WL, MAT, VH, VL, MAT,
                                                        (float*)d_out, nullptr, nullptr, 0, 0, 0, 0);
            gemm_bf3<<<dim3(4, 2, 64), 128, SMEM_DYN, s2>>>(WH, WL, MAT, VH, VL, MAT,
                                                            (float*)d_out, nullptr, nullptr, 0, 0, 2, 0);
        }
        cudaEventRecord(evA1[d], s2);
        cudaStreamWaitEvent(0, evA1[d], 0);
    }
}

// round 17
// speedup vs baseline: 1.0153x; 1.0004x over previous
#include <cuda_runtime.h>
#include <cuda_bf16.h>
#include <cstdint>
#include <cstddef>

#define BATCH 64
#define CH    512
#define LSEQ  512
#define MAT   (CH * LSEQ)
#define NMAT  (BATCH * MAT)
#define EPS   1e-5f

// ---------------- scratch -----------------------------------------------------
__device__ float    g_Y[3ULL * NMAT];        // Q,K,VT pre-BN fp32
__device__ float    g_Wsc[NMAT];             // scores fp32
__device__ uint16_t g_bf[12ULL * NMAT];      // QH,QL,KH,KL,VH,VL,WH,WL,X0H,X0L,X1H,X1L
__device__ uint16_t g_wth[9ULL * MAT];
__device__ uint16_t g_wtl[9ULL * MAT];
__device__ float g_sum[3 * CH];
__device__ float g_sq[3 * CH];

// ---------------- helpers ------------------------------------------------------
__device__ __forceinline__ uint32_t packbf(float a, float b) {
    __nv_bfloat162 t = __floats2bfloat162_rn(a, b);
    return *reinterpret_cast<uint32_t*>(&t);
}
__device__ __forceinline__ float bf16rt(float x) {
    return __bfloat162float(__float2bfloat16(x));
}

#define LDSM4(R, addr) \
    asm volatile("ldmatrix.sync.aligned.m8n8.x4.shared.b16 {%0,%1,%2,%3}, [%4];" \
        : "=r"((R)[0]), "=r"((R)[1]), "=r"((R)[2]), "=r"((R)[3]) : "r"(addr))

__device__ __forceinline__ void mma16816(float* d, const uint32_t* a,
                                         uint32_t b0, uint32_t b1) {
    asm volatile(
        "mma.sync.aligned.m16n8k16.row.col.f32.bf16.bf16.f32 "
        "{%0,%1,%2,%3}, {%4,%5,%6,%7}, {%8,%9}, {%0,%1,%2,%3};"
        : "+f"(d[0]), "+f"(d[1]), "+f"(d[2]), "+f"(d[3])
        : "r"(a[0]), "r"(a[1]), "r"(a[2]), "r"(a[3]), "r"(b0), "r"(b1));
}

#define CP16(dst, src) \
    asm volatile("cp.async.cg.shared.global [%0], [%1], 16;" :: "r"(dst), "l"(src))
#define CPCOMMIT() asm volatile("cp.async.commit_group;" ::: "memory")
#define CPWAIT1()  asm volatile("cp.async.wait_group 1;" ::: "memory")

// ---------------- GEMM core (NT, bf16x3, pre-split operands) -------------------
#define KC 32
#define TILE_B  8192
#define STAGE_B 32768
#define SMEM_DYN (3 * STAGE_B)

__device__ __forceinline__ void gemm_core(
    const uint16_t* __restrict__ Ah, const uint16_t* __restrict__ Al,
    const uint16_t* __restrict__ Bh, const uint16_t* __restrict__ Bl,
    float* __restrict__ CfB, uint16_t* __restrict__ ChB, uint16_t* __restrict__ ClB,
    const float* __restrict__ bias,
    float* __restrict__ sums, float* __restrict__ sqs,
    int m0, int n0, int outMode)
{
    extern __shared__ uint8_t smraw[];
    const uint32_t smemu = (uint32_t)__cvta_generic_to_shared(smraw);
    const int tid  = threadIdx.x;
    const int lane = tid & 31, wid = tid >> 5;

    const int r0 = tid >> 2, k0 = tid & 3;
    const uint32_t dst0 = (uint32_t)(r0 * 64 + ((k0 ^ ((r0 >> 1) & 3)) << 4));
    const char* aH0 = (const char*)(Ah + (size_t)(m0 + r0) * 512 + k0 * 8);
    const char* aL0 = (const char*)(Al + (size_t)(m0 + r0) * 512 + k0 * 8);
    const char* bH0 = (const char*)(Bh + (size_t)(n0 + r0) * 512 + k0 * 8);
    const char* bL0 = (const char*)(Bl + (size_t)(n0 + r0) * 512 + k0 * 8);

    auto issue = [&](int s, int c) {
        const uint32_t sb = smemu + (uint32_t)s * STAGE_B;
        const size_t o = (size_t)c * (KC * 2);
#pragma unroll
        for (int p = 0; p < 4; p++) {
            const uint32_t d = sb + dst0 + p * 2048;
            const size_t so = o + (size_t)p * 32768;
            CP16(d,              aH0 + so);
            CP16(d + TILE_B,     aL0 + so);
            CP16(d + 2 * TILE_B, bH0 + so);
            CP16(d + 3 * TILE_B, bL0 + so);
        }
    };

    const int mw = (wid & 1) * 64;
    const int nw = (wid >> 1) * 64;
    const int lrow = (lane & 7) + 8 * ((lane >> 3) & 1);
    const int lk16 = lane >> 4;
    uint32_t offA[4][2], offB[4][2];
#pragma unroll
    for (int fi = 0; fi < 4; fi++) {
        const int row = mw + fi * 16 + lrow;
        const uint32_t sw = (row >> 1) & 3;
        offA[fi][0] = (uint32_t)(row * 64 + (((0 + lk16) ^ sw) << 4));
        offA[fi][1] = (uint32_t)(row * 64 + (((2 + lk16) ^ sw) << 4));
    }
#pragma unroll
    for (int bj = 0; bj < 4; bj++) {
        const int row = nw + bj * 16 + lrow;
        const uint32_t sw = (row >> 1) & 3;
        offB[bj][0] = (uint32_t)(row * 64 + (((0 + lk16) ^ sw) << 4));
        offB[bj][1] = (uint32_t)(row * 64 + (((2 + lk16) ^ sw) << 4));
    }

    float acc[4][8][4];
#pragma unroll
    for (int i = 0; i < 4; i++)
#pragma unroll
        for (int j = 0; j < 8; j++)
#pragma unroll
            for (int e = 0; e < 4; e++) acc[i][j][e] = 0.f;

    auto compute = [&](int s) {
        const uint32_t sb = smemu + (uint32_t)s * STAGE_B;
#pragma unroll
        for (int kg = 0; kg < 2; kg++) {
            uint32_t Ahr[4][4], Bhr[4][4], Blr[4][4], Alr[4][4];
#pragma unroll
            for (int fi = 0; fi < 4; fi++)
                LDSM4(Ahr[fi], sb + offA[fi][kg]);
#pragma unroll
            for (int bj = 0; bj < 4; bj++)
                LDSM4(Bhr[bj], sb + 2 * TILE_B + offB[bj][kg]);
#pragma unroll
            for (int i = 0; i < 4; i++)
#pragma unroll
                for (int j = 0; j < 8; j++)
                    mma16816(acc[i][j], Ahr[i], Bhr[j >> 1][j & 1], Bhr[j >> 1][(j & 1) + 2]);
#pragma unroll
            for (int bj = 0; bj < 4; bj++)
                LDSM4(Blr[bj], sb + 3 * TILE_B + offB[bj][kg]);
#pragma unroll
            for (int i = 0; i < 4; i++)
#pragma unroll
                for (int j = 0; j < 8; j++)
                    mma16816(acc[i][j], Ahr[i], Blr[j >> 1][j & 1], Blr[j >> 1][(j & 1) + 2]);
#pragma unroll
            for (int fi = 0; fi < 4; fi++)
                LDSM4(Alr[fi], sb + TILE_B + offA[fi][kg]);
#pragma unroll
            for (int i = 0; i < 4; i++)
#pragma unroll
                for (int j = 0; j < 8; j++)
                    mma16816(acc[i][j], Alr[i], Bhr[j >> 1][j & 1], Bhr[j >> 1][(j & 1) + 2]);
        }
    };

    issue(0, 0); CPCOMMIT();
    issue(1, 1); CPCOMMIT();

#pragma unroll 1
    for (int c = 0; c < 16; c++) {
        CPWAIT1();
        __syncthreads();
        if (c + 2 < 16) issue((c + 2) % 3, c + 2);
        CPCOMMIT();
        compute(c % 3);
    }

    // ---------------- epilogue ----------------
    const int rg = lane >> 2;
    const int cg = (lane & 3) * 2;

    float bc[16], cs[16], cq[16];
    if (outMode == 2) {
#pragma unroll
        for (int j = 0; j < 8; j++) {
            bc[2 * j]     = bias[n0 + nw + j * 8 + cg];
            bc[2 * j + 1] = bias[n0 + nw + j * 8 + cg + 1];
        }
#pragma unroll
        for (int e = 0; e < 16; e++) { cs[e] = 0.f; cq[e] = 0.f; }
    }

#pragma unroll
    for (int i = 0; i < 4; i++) {
        const int row0 = m0 + mw + i * 16 + rg;
        const int row1 = row0 + 8;
        float bv0 = 0.f, bv1 = 0.f;
        if (outMode == 1) { bv0 = bias[row0]; bv1 = bias[row1]; }
        float s0 = 0.f, q0 = 0.f, s1 = 0.f, q1 = 0.f;
#pragma unroll
        for (int j = 0; j < 8; j++) {
            float* cc = acc[i][j];
            if (outMode == 1) { cc[0] += bv0; cc[1] += bv0; cc[2] += bv1; cc[3] += bv1; }
            if (outMode == 2) {
                cc[0] += bc[2 * j]; cc[1] += bc[2 * j + 1];
                cc[2] += bc[2 * j]; cc[3] += bc[2 * j + 1];
            }
            const int col = n0 + nw + j * 8 + cg;
            if (outMode == 3) {
                uint32_t* H = (uint32_t*)ChB;
                uint32_t* L = (uint32_t*)ClB;
                const size_t i0 = ((size_t)row0 * 512 + col) >> 1;
                const size_t i1 = ((size_t)row1 * 512 + col) >> 1;
                H[i0] = packbf(cc[0], cc[1]);
                L[i0] = packbf(cc[0] - bf16rt(cc[0]), cc[1] - bf16rt(cc[1]));
                H[i1] = packbf(cc[2], cc[3]);
                L[i1] = packbf(cc[2] - bf16rt(cc[2]), cc[3] - bf16rt(cc[3]));
            } else {
                *(float2*)&CfB[(size_t)row0 * 512 + col] = make_float2(cc[0], cc[1]);
                *(float2*)&CfB[(size_t)row1 * 512 + col] = make_float2(cc[2], cc[3]);
            }
            if (outMode == 1) {
                s0 += cc[0] + cc[1]; q0 += cc[0] * cc[0] + cc[1] * cc[1];
                s1 += cc[2] + cc[3]; q1 += cc[2] * cc[2] + cc[3] * cc[3];
            }
            if (outMode == 2) {
                cs[2 * j]     += cc[0] + cc[2];
                cs[2 * j + 1] += cc[1] + cc[3];
                cq[2 * j]     += cc[0] * cc[0] + cc[2] * cc[2];
                cq[2 * j + 1] += cc[1] * cc[1] + cc[3] * cc[3];
            }
        }
        if (outMode == 1) {
#pragma unroll
            for (int off = 1; off <= 2; off <<= 1) {
                s0 += __shfl_xor_sync(0xffffffffu, s0, off);
                q0 += __shfl_xor_sync(0xffffffffu, q0, off);
                s1 += __shfl_xor_sync(0xffffffffu, s1, off);
                q1 += __shfl_xor_sync(0xffffffffu, q1, off);
            }
            if ((lane & 3) == 0) {
                atomicAdd(&sums[row0], s0); atomicAdd(&sqs[row0], q0);
                atomicAdd(&sums[row1], s1); atomicAdd(&sqs[row1], q1);
            }
        }
    }
    if (outMode == 2) {
#pragma unroll
        for (int e = 0; e < 16; e++) {
#pragma unroll
            for (int off = 4; off <= 16; off <<= 1) {
                cs[e] += __shfl_xor_sync(0xffffffffu, cs[e], off);
                cq[e] += __shfl_xor_sync(0xffffffffu, cq[e], off);
            }
        }
        if (rg == 0) {
#pragma unroll
            for (int j = 0; j < 8; j++) {
                const int col = n0 + nw + j * 8 + cg;
                atomicAdd(&sums[col], cs[2 * j]);         atomicAdd(&sqs[col], cq[2 * j]);
                atomicAdd(&sums[col + 1], cs[2 * j + 1]); atomicAdd(&sqs[col + 1], cq[2 * j + 1]);
            }
        }
    }
}

// standalone GEMM with tile offsets (scores / AV slices)
__global__ __launch_bounds__(128, 2) void gemm_bf3(
    const uint16_t* __restrict__ Ah, const uint16_t* __restrict__ Al, int strideA,
    const uint16_t* __restrict__ Bh, const uint16_t* __restrict__ Bl, int strideB,
    float* __restrict__ Cf,
    uint16_t* __restrict__ Ch, uint16_t* __restrict__ Cl,
    int outMode, int xoff, int yoff, int zoff)
{
    const int b = blockIdx.z + zoff;
    gemm_core(Ah + (size_t)b * strideA, Al + (size_t)b * strideA,
              Bh + (size_t)b * strideB, Bl + (size_t)b * strideB,
              Cf ? Cf + (size_t)b * MAT : nullptr,
              Ch ? Ch + (size_t)b * MAT : nullptr,
              Cl ? Cl + (size_t)b * MAT : nullptr,
              nullptr, nullptr, nullptr,
              (blockIdx.y + yoff) * 128, (blockIdx.x + xoff) * 128, outMode);
}

// fused Q+K projection GEMM: z in [0,128), proj = z>>6, batch = z&63  (mode 1)
__global__ __launch_bounds__(128, 2) void projQK_gemm(
    const uint16_t* __restrict__ wqh, const uint16_t* __restrict__ wql,
    const uint16_t* __restrict__ wkh, const uint16_t* __restrict__ wkl,
    const uint16_t* __restrict__ XiH, const uint16_t* __restrict__ XiL,
    float* __restrict__ Yq, float* __restrict__ Yk,
    const float* __restrict__ bq, const float* __restrict__ bk,
    float* __restrict__ sum, float* __restrict__ sq)
{
    const int proj = blockIdx.z >> 6;
    const int b    = blockIdx.z & 63;
    const size_t xo = (size_t)b * MAT;
    if (proj == 0)
        gemm_core(wqh, wql, XiH + xo, XiL + xo, Yq + xo, nullptr, nullptr,
                  bq, sum, sq, blockIdx.y * 128, blockIdx.x * 128, 1);
    else
        gemm_core(wkh, wkl, XiH + xo, XiL + xo, Yk + xo, nullptr, nullptr,
                  bk, sum + CH, sq + CH, blockIdx.y * 128, blockIdx.x * 128, 1);
}

// V projection GEMM (mode 2, col-stats)
__global__ __launch_bounds__(128, 2) void projV_gemm(
    const uint16_t* __restrict__ XiH, const uint16_t* __restrict__ XiL,
    const uint16_t* __restrict__ wvh, const uint16_t* __restrict__ wvl,
    float* __restrict__ Yv, const float* __restrict__ bv,
    float* __restrict__ sums, float* __restrict__ sqs)
{
    const size_t xo = (size_t)blockIdx.z * MAT;
    gemm_core(XiH + xo, XiL + xo, wvh, wvl, Yv + xo, nullptr, nullptr,
              bv, sums, sqs, blockIdx.y * 128, blockIdx.x * 128, 2);
}

// ---------------- elementwise kernels -------------------------------------------
__global__ void transpose_split(const float* __restrict__ src,
                                uint16_t* __restrict__ H, uint16_t* __restrict__ L)
{
    __shared__ float t[32][33];
    const int b = blockIdx.z;
    const int x0 = blockIdx.x * 32;
    const int y0 = blockIdx.y * 32;
    const float* S = src + (size_t)b * MAT;
    const int tx = threadIdx.x, ty = threadIdx.y;
#pragma unroll
    for (int j = 0; j < 32; j += 8)
        t[ty + j][tx] = S[(size_t)(y0 + ty + j) * 512 + x0 + tx];
    __syncthreads();
    uint16_t* Hb = H + (size_t)b * MAT;
    uint16_t* Lb = L + (size_t)b * MAT;
#pragma unroll
    for (int j = 0; j < 32; j += 8) {
        float v = t[tx][ty + j];
        float h = bf16rt(v);
        const size_t idx = (size_t)(x0 + ty + j) * 512 + y0 + tx;
        __nv_bfloat16 hb = __float2bfloat16(v);
        __nv_bfloat16 lb = __float2bfloat16(v - h);
        Hb[idx] = *reinterpret_cast<uint16_t*>(&hb);
        Lb[idx] = *reinterpret_cast<uint16_t*>(&lb);
    }
}

// convert ONE depth's weights: y selects Wq/Wk/Wv; 8 elems/thread over MAT
__global__ void cvt_splitD(const float* __restrict__ Wq, const float* __restrict__ Wk,
                           const float* __restrict__ Wv,
                           uint16_t* __restrict__ Hall, uint16_t* __restrict__ Lall,
                           int d)
{
    const int w = blockIdx.y;
    const float* src = ((w == 0) ? Wq : (w == 1) ? Wk : Wv) + (size_t)d * MAT;
    uint16_t* H = Hall + ((size_t)w * 3 + d) * MAT;
    uint16_t* L = Lall + ((size_t)w * 3 + d) * MAT;
    const size_t i = (size_t)blockIdx.x * blockDim.x + threadIdx.x;   // over MAT/8
    float4 v0 = ((const float4*)src)[2 * i];
    float4 v1 = ((const float4*)src)[2 * i + 1];
    uint4 h, l;
    h.x = packbf(v0.x, v0.y); h.y = packbf(v0.z, v0.w);
    h.z = packbf(v1.x, v1.y); h.w = packbf(v1.z, v1.w);
    l.x = packbf(v0.x - bf16rt(v0.x), v0.y - bf16rt(v0.y));
    l.y = packbf(v0.z - bf16rt(v0.z), v0.w - bf16rt(v0.w));
    l.z = packbf(v1.x - bf16rt(v1.x), v1.y - bf16rt(v1.y));
    l.w = packbf(v1.z - bf16rt(v1.z), v1.w - bf16rt(v1.w));
    ((uint4*)H)[i] = h;
    ((uint4*)L)[i] = l;
}

__global__ void zero_stats()
{
    int i = blockIdx.x * blockDim.x + threadIdx.x;
    if (i < 3 * CH) { g_sum[i] = 0.f; g_sq[i] = 0.f; }
}

// BN+ReLU+split for Q,K (row layout), 8 elems/thread, inline finalize; y selects Q/K
__global__ void bnqk_split8(
    const float* __restrict__ Yq, const float* __restrict__ Yk,
    const float* __restrict__ gq, const float* __restrict__ betaq,
    const float* __restrict__ gk, const float* __restrict__ betak,
    uint16_t* __restrict__ QH, uint16_t* __restrict__ QL,
    uint16_t* __restrict__ KH, uint16_t* __restrict__ KL)
{
    const size_t i = (size_t)blockIdx.x * blockDim.x + threadIdx.x;   // over NMAT/8
    const int which = blockIdx.y;
    const float* Y  = (which == 0) ? Yq : Yk;
    const float* g  = (which == 0) ? gq : gk;
    const float* be = (which == 0) ? betaq : betak;
    uint16_t* H = (which == 0) ? QH : KH;
    uint16_t* L = (which == 0) ? QL : KL;
    const int so = which * CH;
    const int c = (int)((i >> 6) & 511);
    const float inv_n = 1.0f / (float)(BATCH * LSEQ);
    const float m  = g_sum[so + c] * inv_n;
    const float rs = rsqrtf(g_sq[so + c] * inv_n - m * m + EPS);
    const float sc = rs * g[c];
    const float sh = be[c] - m * sc;
    float4 v0 = ((const float4*)Y)[2 * i];
    float4 v1 = ((const float4*)Y)[2 * i + 1];
    v0.x = fmaxf(fmaf(v0.x, sc, sh), 0.f);
    v0.y = fmaxf(fmaf(v0.y, sc, sh), 0.f);
    v0.z = fmaxf(fmaf(v0.z, sc, sh), 0.f);
    v0.w = fmaxf(fmaf(v0.w, sc, sh), 0.f);
    v1.x = fmaxf(fmaf(v1.x, sc, sh), 0.f);
    v1.y = fmaxf(fmaf(v1.y, sc, sh), 0.f);
    v1.z = fmaxf(fmaf(v1.z, sc, sh), 0.f);
    v1.w = fmaxf(fmaf(v1.w, sc, sh), 0.f);
    uint4 h, l;
    h.x = packbf(v0.x, v0.y); h.y = packbf(v0.z, v0.w);
    h.z = packbf(v1.x, v1.y); h.w = packbf(v1.z, v1.w);
    l.x = packbf(v0.x - bf16rt(v0.x), v0.y - bf16rt(v0.y));
    l.y = packbf(v0.z - bf16rt(v0.z), v0.w - bf16rt(v0.w));
    l.z = packbf(v1.x - bf16rt(v1.x), v1.y - bf16rt(v1.y));
    l.w = packbf(v1.z - bf16rt(v1.z), v1.w - bf16rt(v1.w));
    ((uint4*)H)[i] = h;
    ((uint4*)L)[i] = l;
}

// BN+ReLU+split for V (col layout), 8 elems/thread, inline finalize
__global__ __launch_bounds__(128) void bnv_split8(
    const float* __restrict__ Yv,
    const float* __restrict__ gv, const float* __restrict__ betav,
    uint16_t* __restrict__ VH, uint16_t* __restrict__ VL)
{
    const size_t i = (size_t)blockIdx.x * blockDim.x + threadIdx.x;
    const int c8 = (int)(i & 63);
    const float inv_n = 1.0f / (float)(BATCH * LSEQ);
    float4 v0 = ((const float4*)Yv)[2 * i];
    float4 v1 = ((const float4*)Yv)[2 * i + 1];
    float4 g0 = ((const float4*)gv)[2 * c8];
    float4 g1 = ((const float4*)gv)[2 * c8 + 1];
    float4 b0 = ((const float4*)betav)[2 * c8];
    float4 b1 = ((const float4*)betav)[2 * c8 + 1];
    float4 s0 = *(const float4*)(g_sum + 2 * CH + c8 * 8);
    float4 s1 = *(const float4*)(g_sum + 2 * CH + c8 * 8 + 4);
    float4 q0 = *(const float4*)(g_sq  + 2 * CH + c8 * 8);
    float4 q1 = *(const float4*)(g_sq  + 2 * CH + c8 * 8 + 4);
    float m, rs;
#define BNV1(vv, ss, qq, gg, bb) \
    m = (ss) * inv_n; rs = rsqrtf((qq) * inv_n - m * m + EPS); \
    vv = fmaxf(fmaf(vv, rs * (gg), (bb) - m * rs * (gg)), 0.f);
    BNV1(v0.x, s0.x, q0.x, g0.x, b0.x)
    BNV1(v0.y, s0.y, q0.y, g0.y, b0.y)
    BNV1(v0.z, s0.z, q0.z, g0.z, b0.z)
    BNV1(v0.w, s0.w, q0.w, g0.w, b0.w)
    BNV1(v1.x, s1.x, q1.x, g1.x, b1.x)
    BNV1(v1.y, s1.y, q1.y, g1.y, b1.y)
    BNV1(v1.z, s1.z, q1.z, g1.z, b1.z)
    BNV1(v1.w, s1.w, q1.w, g1.w, b1.w)
#undef BNV1
    uint4 h, l;
    h.x = packbf(v0.x, v0.y); h.y = packbf(v0.z, v0.w);
    h.z = packbf(v1.x, v1.y); h.w = packbf(v1.z, v1.w);
    l.x = packbf(v0.x - bf16rt(v0.x), v0.y - bf16rt(v0.y));
    l.y = packbf(v0.z - bf16rt(v0.z), v0.w - bf16rt(v0.w));
    l.z = packbf(v1.x - bf16rt(v1.x), v1.y - bf16rt(v1.y));
    l.w = packbf(v1.z - bf16rt(v1.z), v1.w - bf16rt(v1.w));
    ((uint4*)VH)[i] = h;
    ((uint4*)VL)[i] = l;
}

// softmax over batch axis, half-slice; slice 0 also zeroes stats for next depth
__global__ void softmax_zero(const float* __restrict__ W,
                             uint16_t* __restrict__ H, uint16_t* __restrict__ L,
                             int blockOff)
{
    if (blockOff == 0 && blockIdx.x < 6) {
        const int z = blockIdx.x * 256 + threadIdx.x;
        g_sum[z] = 0.f; g_sq[z] = 0.f;
    }
    const int cd = (blockIdx.x + blockOff) * blockDim.x + threadIdx.x;
    float v[BATCH];
    float mx = -3.402823e38f;
#pragma unroll
    for (int b = 0; b < BATCH; b++) {
        v[b] = W[(size_t)b * MAT + cd];
        mx = fmaxf(mx, v[b]);
    }
    float s = 0.f;
#pragma unroll
    for (int b = 0; b < BATCH; b++) { v[b] = __expf(v[b] - mx); s += v[b]; }
    const float r = 1.0f / s;
#pragma unroll
    for (int b = 0; b < BATCH; b++) {
        const float z = v[b] * r;
        const float h = bf16rt(z);
        __nv_bfloat16 hb = __float2bfloat16(z);
        __nv_bfloat16 lb = __float2bfloat16(z - h);
        H[(size_t)b * MAT + cd] = *reinterpret_cast<uint16_t*>(&hb);
        L[(size_t)b * MAT + cd] = *reinterpret_cast<uint16_t*>(&lb);
    }
}

// ---------------- orchestration -------------------------------------------------
extern "C" void kernel_launch(void* const* d_in, const int* /*in_sizes*/, int /*n_in*/,
                              void* d_out, int /*out_size*/)
{
    const float* P     = (const float*)d_in[0];
    const float* Wq    = (const float*)d_in[1];
    const float* bq    = (const float*)d_in[2];
    const float* gq    = (const float*)d_in[3];
    const float* betaq = (const float*)d_in[4];
    const float* Wk    = (const float*)d_in[5];
    const float* bk    = (const float*)d_in[6];
    const float* gk    = (const float*)d_in[7];
    const float* betak = (const float*)d_in[8];
    const float* Wv    = (const float*)d_in[9];
    const float* bv    = (const float*)d_in[10];
    const float* gv    = (const float*)d_in[11];
    const float* betav = (const float*)d_in[12];

    cudaFuncSetAttribute(gemm_bf3,    cudaFuncAttributeMaxDynamicSharedMemorySize, SMEM_DYN);
    cudaFuncSetAttribute(projQK_gemm, cudaFuncAttributeMaxDynamicSharedMemorySize, SMEM_DYN);
    cudaFuncSetAttribute(projV_gemm,  cudaFuncAttributeMaxDynamicSharedMemorySize, SMEM_DYN);

    float *Y, *Wsc, *sum, *sq;
    uint16_t *bf, *wth, *wtl;
    cudaGetSymbolAddress((void**)&Y,   g_Y);
    cudaGetSymbolAddress((void**)&Wsc, g_Wsc);
    cudaGetSymbolAddress((void**)&bf,  g_bf);
    cudaGetSymbolAddress((void**)&wth, g_wth);
    cudaGetSymbolAddress((void**)&wtl, g_wtl);
    cudaGetSymbolAddress((void**)&sum, g_sum);
    cudaGetSymbolAddress((void**)&sq,  g_sq);

    uint16_t* QH  = bf;
    uint16_t* QL  = bf + 1ULL * NMAT;
    uint16_t* KH  = bf + 2ULL * NMAT;
    uint16_t* KL  = bf + 3ULL * NMAT;
    uint16_t* VH  = bf + 4ULL * NMAT;
    uint16_t* VL  = bf + 5ULL * NMAT;
    uint16_t* WH  = bf + 6ULL * NMAT;
    uint16_t* WL  = bf + 7ULL * NMAT;
    uint16_t* X0H = bf + 8ULL * NMAT;
    uint16_t* X0L = bf + 9ULL * NMAT;
    uint16_t* X1H = bf + 10ULL * NMAT;
    uint16_t* X1L = bf + 11ULL * NMAT;

    float* Yq = Y;
    float* Yk = Y + 1ULL * NMAT;
    float* Yv = Y + 2ULL * NMAT;

    cudaStream_t s2;
    cudaStreamCreateWithFlags(&s2, cudaStreamNonBlocking);
    cudaEvent_t e0, e1;
    cudaEvent_t evQK[3], evP[3], evBN[3], evSA[3], evSB[3], evA1[3];
    cudaEventCreateWithFlags(&e0, cudaEventDisableTiming);
    cudaEventCreateWithFlags(&e1, cudaEventDisableTiming);
    for (int d = 0; d < 3; d++) {
        cudaEventCreateWithFlags(&evQK[d], cudaEventDisableTiming);
        cudaEventCreateWithFlags(&evP[d],  cudaEventDisableTiming);
        cudaEventCreateWithFlags(&evBN[d], cudaEventDisableTiming);
        cudaEventCreateWithFlags(&evSA[d], cudaEventDisableTiming);
        cudaEventCreateWithFlags(&evSB[d], cudaEventDisableTiming);
        cudaEventCreateWithFlags(&evA1[d], cudaEventDisableTiming);
    }

    // prologue: depth-0 weights + stats on s2, transpose on main, join
    cudaEventRecord(e0, 0);
    cudaStreamWaitEvent(s2, e0, 0);
    cvt_splitD<<<dim3(MAT / 8 / 256, 3), 256, 0, s2>>>(Wq, Wk, Wv, wth, wtl, 0);
    zero_stats<<<6, 256, 0, s2>>>();
    cudaEventRecord(e1, s2);
    transpose_split<<<dim3(16, 16, BATCH), dim3(32, 8)>>>(P, X0H, X0L);
    cudaStreamWaitEvent(0, e1, 0);

    for (int d = 0; d < 3; d++) {
        uint16_t* XiH = (d == 1) ? X1H : X0H;
        uint16_t* XiL = (d == 1) ? X1L : X0L;
        uint16_t* XoH = (d == 0) ? X1H : X0H;
        uint16_t* XoL = (d == 0) ? X1L : X0L;

        const uint16_t* wqh = wth + (0ULL * 3 + d) * MAT;
        const uint16_t* wql = wtl + (0ULL * 3 + d) * MAT;
        const uint16_t* wkh = wth + (1ULL * 3 + d) * MAT;
        const uint16_t* wkl = wtl + (1ULL * 3 + d) * MAT;
        const uint16_t* wvh = wth + (2ULL * 3 + d) * MAT;
        const uint16_t* wvl = wtl + (2ULL * 3 + d) * MAT;

        // main: Q+K projections, then V projection
        projQK_gemm<<<dim3(4, 4, 2 * BATCH), 128, SMEM_DYN>>>(
            wqh, wql, wkh, wkl, XiH, XiL, Yq, Yk,
            bq + d * CH, bk + d * CH, sum, sq);
        cudaEventRecord(evQK[d], 0);
        projV_gemm<<<dim3(4, 4, BATCH), 128, SMEM_DYN>>>(
            XiH, XiL, wvh, wvl, Yv, bv + d * CH, sum + 2 * CH, sq + 2 * CH);
        cudaEventRecord(evP[d], 0);

        // s2: next-depth weight conversion rides in the idle window before evQK
        if (d < 2)
            cvt_splitD<<<dim3(MAT / 8 / 256, 3), 256, 0, s2>>>(Wq, Wk, Wv, wth, wtl, d + 1);

        // s2: bnqk under projV; bnv under scoresA
        cudaStreamWaitEvent(s2, evQK[d], 0);
        bnqk_split8<<<dim3(NMAT / 8 / 256, 2), 256, 0, s2>>>(
            Yq, Yk, gq + d * CH, betaq + d * CH, gk + d * CH, betak + d * CH,
            QH, QL, KH, KL);
        cudaEventRecord(evBN[d], s2);
        cudaStreamWaitEvent(s2, evP[d], 0);
        bnv_split8<<<NMAT / 8 / 128, 128, 0, s2>>>(Yv, gv + d * CH, betav + d * CH, VH, VL);

        // scores: main batches 0..31 (after bn), s2 batches 32..63 (in-order after bnv)
        cudaStreamWaitEvent(0, evBN[d], 0);
        gemm_bf3<<<dim3(4, 4, 32), 128, SMEM_DYN>>>(QH, QL, MAT, KH, KL, MAT,
                                                    Wsc, nullptr, nullptr, 0, 0, 0, 0);
        cudaEventRecord(evSA[d], 0);
        gemm_bf3<<<dim3(4, 4, 32), 128, SMEM_DYN, s2>>>(QH, QL, MAT, KH, KL, MAT,
                                                        Wsc, nullptr, nullptr, 0, 0, 0, 32);
        cudaEventRecord(evSB[d], s2);

        // softmax halves (each needs ALL batches of scores)
        cudaStreamWaitEvent(0, evSB[d], 0);
        softmax_zero<<<MAT / 256 / 2, 256>>>(Wsc, WH, WL, 0);               // c < 256 (+ stat zero)
        cudaStreamWaitEvent(s2, evSA[d], 0);
        softmax_zero<<<MAT / 256 / 2, 256, 0, s2>>>(Wsc, WH, WL, MAT / 256 / 2);  // c >= 256

        if (d < 2) {
            // xT_next[l][c] = VT x w ; out cols c -> slice by x
            gemm_bf3<<<dim3(2, 4, 64), 128, SMEM_DYN>>>(VH, VL, MAT, WH, WL, MAT,
                                                        nullptr, XoH, XoL, 3, 0, 0, 0);
            gemm_bf3<<<dim3(2, 4, 64), 128, SMEM_DYN, s2>>>(VH, VL, MAT, WH, WL, MAT,
                                                            nullptr, XoH, XoL, 3, 2, 0, 0);
        } else {
            // out[c][l] = w x VT ; out rows c -> slice by y
            gemm_bf3<<<dim3(4, 2, 64), 128, SMEM_DYN>>>(WH, WL, MAT, VH, VL, MAT,
                                                        (float*)d_out, nullptr, nullptr, 0, 0, 0, 0);
            gemm_bf3<<<dim3(4, 2, 64), 128, SMEM_DYN, s2>>>(WH, WL, MAT, VH, VL, MAT,
                                                            (float*)d_out, nullptr, nullptr, 0, 0, 2, 0);
        }
        cudaEventRecord(evA1[d], s2);
        cudaStreamWaitEvent(0, evA1[d], 0);
    }
}